// round 9
// baseline (speedup 1.0000x reference)
#include <cuda_runtime.h>

// QuadraticProjectionLoss — fused single kernel, spill-free layout
//   B=8192, V=8, J=32
//   inputs: K [B,V,3,3] f32, cam_preds [B,V,3,4] f32,
//           kps_world_pred [B,J,3] f32, initial_keypoints [B,V,J,2] f32
//   output: scalar f32
//
// warp u = half-batch: b = u>>1, views v = (u&1)*4 + (lane>>3)
// lane group g = lane&7 handles 4 keypoints j = g*4 .. g*4+3
// => per-lane live state ~45 regs (M[12] + 12 kps + 8 init), no spills.

#define BB 8192
#define VV 8
#define JJ 32
#define NBLK 2048                    // 16384 warps = 2 warps per batch
#define THRESH 100.0f
#define POW_C 63.095734448019324f    // 100^0.9

__device__ float    g_partials[NBLK];
__device__ unsigned g_count = 0;     // self-resetting completion counter

__global__ __launch_bounds__(256) void qpl_fused(
    const float* __restrict__ K_g,
    const float* __restrict__ cam_g,
    const float* __restrict__ kps_g,
    const float* __restrict__ init_g,
    float* __restrict__ out)
{
    const int wid  = threadIdx.x >> 5;
    const int u    = blockIdx.x * 8 + wid;      // half-batch index
    const int b    = u >> 1;
    const int lane = threadIdx.x & 31;
    const int v    = ((u & 1) << 2) + (lane >> 3);  // view 0..7
    const int g    = lane & 7;                       // kp group (4 kps)

    // ---- batch all loads up front (high MLP, all independent) ----
    // world keypoints: 4 kps = 12 floats = 3 float4 (48B-aligned)
    const float4* kp4 = reinterpret_cast<const float4*>(
        kps_g + (size_t)b * (JJ * 3) + g * 12);
    const float4 ka = kp4[0], kb = kp4[1], kc = kp4[2];

    // initial keypoints: 4 float2 = 2 float4 (32B-aligned)
    const float4* i4 = reinterpret_cast<const float4*>(
        init_g + (((size_t)b * VV + v) * JJ + g * 4) * 2);
    const float4 ia = i4[0], ib = i4[1];

    // cam [3x4]: 3 float4 (48B-aligned)
    const float4* c4 = reinterpret_cast<const float4*>(
        cam_g + ((size_t)b * VV + v) * 12);
    const float4 c0 = c4[0], c1 = c4[1], c2 = c4[2];

    // K [3x3]: 9 scalars (36B stride, not float4-alignable)
    const float* kmp = K_g + ((size_t)b * VV + v) * 9;
    float kk[9];
    #pragma unroll
    for (int i = 0; i < 9; i++) kk[i] = kmp[i];

    // ---- M = K(3x3) @ cam(3x4) ----
    float M[12];
    {
        const float ca[12] = {c0.x,c0.y,c0.z,c0.w, c1.x,c1.y,c1.z,c1.w, c2.x,c2.y,c2.z,c2.w};
        #pragma unroll
        for (int r = 0; r < 3; r++)
            #pragma unroll
            for (int c = 0; c < 4; c++)
                M[r*4+c] = fmaf(kk[r*3+0], ca[c],
                           fmaf(kk[r*3+1], ca[4+c],
                                kk[r*3+2] * ca[8+c]));
    }

    const float kf[12]  = {ka.x,ka.y,ka.z,ka.w, kb.x,kb.y,kb.z,kb.w, kc.x,kc.y,kc.z,kc.w};
    const float ikf[8]  = {ia.x,ia.y,ia.z,ia.w, ib.x,ib.y,ib.z,ib.w};

    // ---- 4 keypoints per lane ----
    float s_pn = 0.0f, s_in = 0.0f, s_d = 0.0f;
    #pragma unroll
    for (int k = 0; k < 4; k++) {
        const float X = kf[3*k], Y = kf[3*k+1], Z = kf[3*k+2];
        const float i0 = fmaf(M[0], X, fmaf(M[1], Y, fmaf(M[2],  Z, M[3])));
        const float i1 = fmaf(M[4], X, fmaf(M[5], Y, fmaf(M[6],  Z, M[7])));
        const float i2 = fmaf(M[8], X, fmaf(M[9], Y, fmaf(M[10], Z, M[11])));
        const float inv = __fdividef(1.0f, i2);
        const float px = i0 * inv;
        const float py = i1 * inv;
        const float ix = ikf[2*k], iy = ikf[2*k+1];

        s_pn = fmaf(px, px, fmaf(py, py, s_pn));
        s_in = fmaf(ix, ix, fmaf(iy, iy, s_in));

        float dx = (px - ix) * 0.1f; dx *= dx;
        float dy = (py - iy) * 0.1f; dy *= dy;
        if (dx > THRESH) dx = __powf(dx, 0.1f) * POW_C;
        if (dy > THRESH) dy = __powf(dy, 0.1f) * POW_C;
        s_d += dx + dy;
    }

    // ---- reduce over g (lane bits 0..2 = same view) ----
    #pragma unroll
    for (int o = 1; o <= 4; o <<= 1) {
        s_pn += __shfl_xor_sync(0xffffffffu, s_pn, o);
        s_in += __shfl_xor_sync(0xffffffffu, s_in, o);
        s_d  += __shfl_xor_sync(0xffffffffu, s_d,  o);
    }

    // per-view loss (identical on all 8 lanes of a view)
    const float penal = fabsf(sqrtf(s_pn) * rsqrtf(s_in) - 1.0f);
    float loss = 0.5f * s_d * penal;

    // sum the 4 views of this warp (lane bits 3,4 = view dimension)
    loss += __shfl_xor_sync(0xffffffffu, loss, 8);
    loss += __shfl_xor_sync(0xffffffffu, loss, 16);

    __shared__ float sh[8];
    if (lane == 0) sh[wid] = loss;
    __syncthreads();

    __shared__ bool isLast;
    if (threadIdx.x == 0) {
        float t = 0.0f;
        #pragma unroll
        for (int i = 0; i < 8; i++) t += sh[i];   // fixed order
        g_partials[blockIdx.x] = t;
        __threadfence();
        unsigned old = atomicAdd(&g_count, 1u);
        isLast = (old == (unsigned)(gridDim.x - 1));
    }
    __syncthreads();

    // ---- last block: deterministic final reduction over 2048 partials ----
    if (isLast) {
        double acc = 0.0;
        #pragma unroll
        for (int i = 0; i < NBLK / 256; i++)
            acc += (double)g_partials[threadIdx.x + i * 256];

        __shared__ double shd[256];
        shd[threadIdx.x] = acc;
        __syncthreads();
        #pragma unroll
        for (int s = 128; s; s >>= 1) {
            if (threadIdx.x < s) shd[threadIdx.x] += shd[threadIdx.x + s];
            __syncthreads();
        }
        if (threadIdx.x == 0) {
            out[0] = (float)(shd[0] / (double)(BB * VV));
            g_count = 0;                          // reset for next graph replay
        }
    }
}

extern "C" void kernel_launch(void* const* d_in, const int* in_sizes, int n_in,
                              void* d_out, int out_size)
{
    const float* K    = (const float*)d_in[0];
    const float* cam  = (const float*)d_in[1];
    const float* kps  = (const float*)d_in[2];
    const float* init = (const float*)d_in[3];

    qpl_fused<<<NBLK, 256>>>(K, cam, kps, init, (float*)d_out);
}

// round 13
// speedup vs baseline: 1.3074x; 1.3074x over previous
#include <cuda_runtime.h>

// QuadraticProjectionLoss — fused kernel with block-cooperative smem staging
//   B=8192, V=8, J=32
//   inputs: K [B,V,3,3] f32, cam_preds [B,V,3,4] f32,
//           kps_world_pred [B,J,3] f32, initial_keypoints [B,V,J,2] f32
//   output: scalar f32
//
// Block = 8 warps = 4 batches. Warp u: b = u>>1, lane -> view v (4/warp),
// kp-group g (4 kps each). K/cam/kps staged via ~1 coalesced LDG.128 per
// thread into smem (kills the 17-LDG/warp L1tex-queue contention that was
// stretching CTA time ~2x); only init_keypoints streams directly from DRAM.

#define BB 8192
#define VV 8
#define JJ 32
#define NBLK 2048                    // 8 warps/block, 2 warps per batch
#define THRESH 100.0f
#define POW_C 63.095734448019324f    // 100^0.9

__device__ float    g_partials[NBLK];
__device__ unsigned g_count = 0;     // self-resetting completion counter

__global__ __launch_bounds__(256) void qpl_fused(
    const float* __restrict__ K_g,
    const float* __restrict__ cam_g,
    const float* __restrict__ kps_g,
    const float* __restrict__ init_g,
    float* __restrict__ out)
{
    const int tid  = threadIdx.x;
    const int wid  = tid >> 5;
    const int u    = blockIdx.x * 8 + wid;           // half-batch index
    const int b    = u >> 1;
    const int bi   = wid >> 1;                       // batch within block (0..3)
    const int lane = tid & 31;
    const int v    = ((u & 1) << 2) + (lane >> 3);   // view 0..7
    const int g    = lane & 7;                       // kp group (4 kps)

    // ---- init keypoints: direct DRAM stream, issued first (long pole) ----
    const float4* i4 = reinterpret_cast<const float4*>(
        init_g + (((size_t)b * VV + v) * JJ + g * 4) * 2);
    const float4 iA = i4[0], iB = i4[1];

    // ---- cooperative staging of K / cam / kps for the block's 4 batches ----
    __shared__ float4 s_stage[264];                  // 96 kps4 + 96 cam4 + 72 K4
    float* s_kps = reinterpret_cast<float*>(s_stage);        // 384 floats
    float* s_cam = s_kps + 384;                               // 384 floats
    float* s_K   = s_cam + 384;                               // 288 floats
    {
        const size_t b0 = (size_t)blockIdx.x * 4;
        if (tid < 96) {
            s_stage[tid] =
                reinterpret_cast<const float4*>(kps_g + b0 * (JJ * 3))[tid];
            s_stage[96 + tid] =
                reinterpret_cast<const float4*>(cam_g + b0 * (VV * 12))[tid];
        }
        if (tid < 72) {
            s_stage[192 + tid] =
                reinterpret_cast<const float4*>(K_g + b0 * (VV * 9))[tid];
        }
    }
    __syncthreads();

    // ---- per-lane reads from smem (conflict-free: broadcast / distinct banks) ----
    const float4 kA = *reinterpret_cast<const float4*>(s_kps + bi * 96 + g * 12);
    const float4 kB = *reinterpret_cast<const float4*>(s_kps + bi * 96 + g * 12 + 4);
    const float4 kC = *reinterpret_cast<const float4*>(s_kps + bi * 96 + g * 12 + 8);

    const float4 c0 = *reinterpret_cast<const float4*>(s_cam + bi * 96 + v * 12);
    const float4 c1 = *reinterpret_cast<const float4*>(s_cam + bi * 96 + v * 12 + 4);
    const float4 c2 = *reinterpret_cast<const float4*>(s_cam + bi * 96 + v * 12 + 8);

    const float* kp = s_K + bi * 72 + v * 9;
    const float k0 = kp[0], k1 = kp[1], k2 = kp[2];
    const float k3 = kp[3], k4 = kp[4], k5 = kp[5];
    const float k6 = kp[6], k7 = kp[7], k8 = kp[8];

    // ---- M = K(3x3) @ cam(3x4), fully scalar (no local arrays) ----
    const float m00 = fmaf(k0, c0.x, fmaf(k1, c1.x, k2 * c2.x));
    const float m01 = fmaf(k0, c0.y, fmaf(k1, c1.y, k2 * c2.y));
    const float m02 = fmaf(k0, c0.z, fmaf(k1, c1.z, k2 * c2.z));
    const float m03 = fmaf(k0, c0.w, fmaf(k1, c1.w, k2 * c2.w));
    const float m10 = fmaf(k3, c0.x, fmaf(k4, c1.x, k5 * c2.x));
    const float m11 = fmaf(k3, c0.y, fmaf(k4, c1.y, k5 * c2.y));
    const float m12 = fmaf(k3, c0.z, fmaf(k4, c1.z, k5 * c2.z));
    const float m13 = fmaf(k3, c0.w, fmaf(k4, c1.w, k5 * c2.w));
    const float m20 = fmaf(k6, c0.x, fmaf(k7, c1.x, k8 * c2.x));
    const float m21 = fmaf(k6, c0.y, fmaf(k7, c1.y, k8 * c2.y));
    const float m22 = fmaf(k6, c0.z, fmaf(k7, c1.z, k8 * c2.z));
    const float m23 = fmaf(k6, c0.w, fmaf(k7, c1.w, k8 * c2.w));

    float s_pn = 0.0f, s_in = 0.0f, s_d = 0.0f;

#define KP_STEP(X, Y, Z, IX, IY) do {                                          \
        const float i0_ = fmaf(m00, (X), fmaf(m01, (Y), fmaf(m02, (Z), m03))); \
        const float i1_ = fmaf(m10, (X), fmaf(m11, (Y), fmaf(m12, (Z), m13))); \
        const float i2_ = fmaf(m20, (X), fmaf(m21, (Y), fmaf(m22, (Z), m23))); \
        const float inv_ = __fdividef(1.0f, i2_);                              \
        const float px_ = i0_ * inv_;                                          \
        const float py_ = i1_ * inv_;                                          \
        s_pn = fmaf(px_, px_, fmaf(py_, py_, s_pn));                           \
        s_in = fmaf((IX), (IX), fmaf((IY), (IY), s_in));                       \
        float dx_ = (px_ - (IX)) * 0.1f; dx_ *= dx_;                           \
        float dy_ = (py_ - (IY)) * 0.1f; dy_ *= dy_;                           \
        if (dx_ > THRESH) dx_ = __powf(dx_, 0.1f) * POW_C;                     \
        if (dy_ > THRESH) dy_ = __powf(dy_, 0.1f) * POW_C;                     \
        s_d += dx_ + dy_;                                                      \
    } while (0)

    KP_STEP(kA.x, kA.y, kA.z, iA.x, iA.y);
    KP_STEP(kA.w, kB.x, kB.y, iA.z, iA.w);
    KP_STEP(kB.z, kB.w, kC.x, iB.x, iB.y);
    KP_STEP(kC.y, kC.z, kC.w, iB.z, iB.w);
#undef KP_STEP

    // ---- reduce over g (lane bits 0..2 = same view) ----
    #pragma unroll
    for (int o = 1; o <= 4; o <<= 1) {
        s_pn += __shfl_xor_sync(0xffffffffu, s_pn, o);
        s_in += __shfl_xor_sync(0xffffffffu, s_in, o);
        s_d  += __shfl_xor_sync(0xffffffffu, s_d,  o);
    }

    const float penal = fabsf(sqrtf(s_pn) * rsqrtf(s_in) - 1.0f);
    float loss = 0.5f * s_d * penal;                 // identical across a view's lanes

    // sum this warp's 4 views (lane bits 3,4)
    loss += __shfl_xor_sync(0xffffffffu, loss, 8);
    loss += __shfl_xor_sync(0xffffffffu, loss, 16);

    __shared__ float sh[8];
    if (lane == 0) sh[wid] = loss;
    __syncthreads();

    __shared__ bool isLast;
    if (tid == 0) {
        float t = 0.0f;
        #pragma unroll
        for (int i = 0; i < 8; i++) t += sh[i];      // fixed order
        g_partials[blockIdx.x] = t;
        __threadfence();
        unsigned old = atomicAdd(&g_count, 1u);
        isLast = (old == (unsigned)(gridDim.x - 1));
    }
    __syncthreads();

    // ---- last block: deterministic final reduction over 2048 partials ----
    if (isLast) {
        double acc = 0.0;
        #pragma unroll
        for (int i = 0; i < NBLK / 256; i++)
            acc += (double)g_partials[tid + i * 256];

        __shared__ double shd[256];
        shd[tid] = acc;
        __syncthreads();
        #pragma unroll
        for (int s = 128; s; s >>= 1) {
            if (tid < s) shd[tid] += shd[tid + s];
            __syncthreads();
        }
        if (tid == 0) {
            out[0] = (float)(shd[0] / (double)(BB * VV));
            g_count = 0;                             // reset for next graph replay
        }
    }
}

extern "C" void kernel_launch(void* const* d_in, const int* in_sizes, int n_in,
                              void* d_out, int out_size)
{
    const float* K    = (const float*)d_in[0];
    const float* cam  = (const float*)d_in[1];
    const float* kps  = (const float*)d_in[2];
    const float* init = (const float*)d_in[3];

    qpl_fused<<<NBLK, 256>>>(K, cam, kps, init, (float*)d_out);
}

// round 14
// speedup vs baseline: 1.4881x; 1.1382x over previous
#include <cuda_runtime.h>

// QuadraticProjectionLoss — fused kernel, branchless loss + padded-K staging
//   B=8192, V=8, J=32
//   inputs: K [B,V,3,3] f32, cam_preds [B,V,3,4] f32,
//           kps_world_pred [B,J,3] f32, initial_keypoints [B,V,J,2] f32
//   output: scalar f32
//
// Block = 8 warps = 4 batches; warp u: b=u>>1, lane -> view v (4/warp),
// kp-group g (4 kps). Smooth-MSE select replaced by the exact identity
//   d' = min(d, d^0.1 * 100^0.9)   (curves cross at d=100, pow-form larger below)
// which removes all branches from the hot loop.

#define BB 8192
#define VV 8
#define JJ 32
#define NBLK 2048                    // 8 warps/block, 2 warps per batch
#define POW_C 63.095734448019324f    // 100^0.9

__device__ float    g_partials[NBLK];
__device__ unsigned g_count = 0;     // self-resetting completion counter

__global__ __launch_bounds__(256, 7) void qpl_fused(
    const float* __restrict__ K_g,
    const float* __restrict__ cam_g,
    const float* __restrict__ kps_g,
    const float* __restrict__ init_g,
    float* __restrict__ out)
{
    const int tid  = threadIdx.x;
    const int wid  = tid >> 5;
    const int u    = blockIdx.x * 8 + wid;           // half-batch index
    const int b    = u >> 1;
    const int bi   = wid >> 1;                       // batch within block (0..3)
    const int lane = tid & 31;
    const int v    = ((u & 1) << 2) + (lane >> 3);   // view 0..7
    const int g    = lane & 7;                       // kp group (4 kps)

    // ---- init keypoints: direct DRAM stream, issued first (long pole) ----
    const float4* i4 = reinterpret_cast<const float4*>(
        init_g + (((size_t)b * VV + v) * JJ + g * 4) * 2);
    const float4 iA = i4[0], iB = i4[1];

    // ---- cooperative staging: kps + cam (float4), K padded to 12-float slots ----
    __shared__ float4 s_stage[192];                  // 96 kps4 + 96 cam4
    __shared__ float  s_K[384];                      // 4 batches * 8 views * 12 (9 used)
    float* s_kps = reinterpret_cast<float*>(s_stage);        // 384 floats
    float* s_cam = s_kps + 384;                               // 384 floats
    {
        const size_t b0 = (size_t)blockIdx.x * 4;
        if (tid < 96) {
            s_stage[tid] =
                reinterpret_cast<const float4*>(kps_g + b0 * (JJ * 3))[tid];
            s_stage[96 + tid] =
                reinterpret_cast<const float4*>(cam_g + b0 * (VV * 12))[tid];
        }
        // K: 288 source floats -> padded slots (i/9)*12 + i%9
        #pragma unroll
        for (int it = 0; it < 2; it++) {
            int i = tid + it * 256;
            if (i < 288) {
                int q = i / 9, r = i - q * 9;
                s_K[q * 12 + r] = K_g[b0 * (VV * 9) + i];
            }
        }
    }
    __syncthreads();

    // ---- per-lane reads from smem ----
    const float4 kA = *reinterpret_cast<const float4*>(s_kps + bi * 96 + g * 12);
    const float4 kB = *reinterpret_cast<const float4*>(s_kps + bi * 96 + g * 12 + 4);
    const float4 kC = *reinterpret_cast<const float4*>(s_kps + bi * 96 + g * 12 + 8);

    const float4 c0 = *reinterpret_cast<const float4*>(s_cam + bi * 96 + v * 12);
    const float4 c1 = *reinterpret_cast<const float4*>(s_cam + bi * 96 + v * 12 + 4);
    const float4 c2 = *reinterpret_cast<const float4*>(s_cam + bi * 96 + v * 12 + 8);

    const float4 kq0 = *reinterpret_cast<const float4*>(s_K + (bi * 8 + v) * 12);
    const float4 kq1 = *reinterpret_cast<const float4*>(s_K + (bi * 8 + v) * 12 + 4);
    const float  k8  = s_K[(bi * 8 + v) * 12 + 8];
    const float k0 = kq0.x, k1 = kq0.y, k2 = kq0.z, k3 = kq0.w;
    const float k4 = kq1.x, k5 = kq1.y, k6 = kq1.z, k7 = kq1.w;

    // ---- M = K(3x3) @ cam(3x4), fully scalar ----
    const float m00 = fmaf(k0, c0.x, fmaf(k1, c1.x, k2 * c2.x));
    const float m01 = fmaf(k0, c0.y, fmaf(k1, c1.y, k2 * c2.y));
    const float m02 = fmaf(k0, c0.z, fmaf(k1, c1.z, k2 * c2.z));
    const float m03 = fmaf(k0, c0.w, fmaf(k1, c1.w, k2 * c2.w));
    const float m10 = fmaf(k3, c0.x, fmaf(k4, c1.x, k5 * c2.x));
    const float m11 = fmaf(k3, c0.y, fmaf(k4, c1.y, k5 * c2.y));
    const float m12 = fmaf(k3, c0.z, fmaf(k4, c1.z, k5 * c2.z));
    const float m13 = fmaf(k3, c0.w, fmaf(k4, c1.w, k5 * c2.w));
    const float m20 = fmaf(k6, c0.x, fmaf(k7, c1.x, k8 * c2.x));
    const float m21 = fmaf(k6, c0.y, fmaf(k7, c1.y, k8 * c2.y));
    const float m22 = fmaf(k6, c0.z, fmaf(k7, c1.z, k8 * c2.z));
    const float m23 = fmaf(k6, c0.w, fmaf(k7, c1.w, k8 * c2.w));

    float s_pn = 0.0f, s_in = 0.0f, s_d = 0.0f;

    // branchless smooth-MSE: min(d, d^0.1 * 100^0.9) == reference select
#define KP_STEP(X, Y, Z, IX, IY) do {                                          \
        const float i0_ = fmaf(m00, (X), fmaf(m01, (Y), fmaf(m02, (Z), m03))); \
        const float i1_ = fmaf(m10, (X), fmaf(m11, (Y), fmaf(m12, (Z), m13))); \
        const float i2_ = fmaf(m20, (X), fmaf(m21, (Y), fmaf(m22, (Z), m23))); \
        const float inv_ = __fdividef(1.0f, i2_);                              \
        const float px_ = i0_ * inv_;                                          \
        const float py_ = i1_ * inv_;                                          \
        s_pn = fmaf(px_, px_, fmaf(py_, py_, s_pn));                           \
        s_in = fmaf((IX), (IX), fmaf((IY), (IY), s_in));                       \
        float dx_ = (px_ - (IX)) * 0.1f; dx_ *= dx_;                           \
        float dy_ = (py_ - (IY)) * 0.1f; dy_ *= dy_;                           \
        dx_ = fminf(dx_, __powf(dx_, 0.1f) * POW_C);                           \
        dy_ = fminf(dy_, __powf(dy_, 0.1f) * POW_C);                           \
        s_d += dx_ + dy_;                                                      \
    } while (0)

    KP_STEP(kA.x, kA.y, kA.z, iA.x, iA.y);
    KP_STEP(kA.w, kB.x, kB.y, iA.z, iA.w);
    KP_STEP(kB.z, kB.w, kC.x, iB.x, iB.y);
    KP_STEP(kC.y, kC.z, kC.w, iB.z, iB.w);
#undef KP_STEP

    // ---- reduce over g (lane bits 0..2 = same view) ----
    #pragma unroll
    for (int o = 1; o <= 4; o <<= 1) {
        s_pn += __shfl_xor_sync(0xffffffffu, s_pn, o);
        s_in += __shfl_xor_sync(0xffffffffu, s_in, o);
        s_d  += __shfl_xor_sync(0xffffffffu, s_d,  o);
    }

    const float penal = fabsf(sqrtf(s_pn) * rsqrtf(s_in) - 1.0f);
    float loss = 0.5f * s_d * penal;                 // identical across a view's lanes

    // sum this warp's 4 views (lane bits 3,4)
    loss += __shfl_xor_sync(0xffffffffu, loss, 8);
    loss += __shfl_xor_sync(0xffffffffu, loss, 16);

    __shared__ float sh[8];
    if (lane == 0) sh[wid] = loss;
    __syncthreads();

    __shared__ bool isLast;
    if (tid == 0) {
        float t = 0.0f;
        #pragma unroll
        for (int i = 0; i < 8; i++) t += sh[i];      // fixed order
        g_partials[blockIdx.x] = t;
        __threadfence();
        unsigned old = atomicAdd(&g_count, 1u);
        isLast = (old == (unsigned)(gridDim.x - 1));
    }
    __syncthreads();

    // ---- last block: deterministic final reduction over 2048 partials ----
    if (isLast) {
        double acc = 0.0;
        #pragma unroll
        for (int i = 0; i < NBLK / 256; i++)
            acc += (double)g_partials[tid + i * 256];

        __shared__ double shd[256];
        shd[tid] = acc;
        __syncthreads();
        #pragma unroll
        for (int s = 128; s; s >>= 1) {
            if (tid < s) shd[tid] += shd[tid + s];
            __syncthreads();
        }
        if (tid == 0) {
            out[0] = (float)(shd[0] / (double)(BB * VV));
            g_count = 0;                             // reset for next graph replay
        }
    }
}

extern "C" void kernel_launch(void* const* d_in, const int* in_sizes, int n_in,
                              void* d_out, int out_size)
{
    const float* K    = (const float*)d_in[0];
    const float* cam  = (const float*)d_in[1];
    const float* kps  = (const float*)d_in[2];
    const float* init = (const float*)d_in[3];

    qpl_fused<<<NBLK, 256>>>(K, cam, kps, init, (float*)d_out);
}

// round 15
// speedup vs baseline: 1.6887x; 1.1348x over previous
#include <cuda_runtime.h>

// QuadraticProjectionLoss — single-wave fused kernel (2 chunks/block)
//   B=8192, V=8, J=32
//   inputs: K [B,V,3,3] f32, cam_preds [B,V,3,4] f32,
//           kps_world_pred [B,J,3] f32, initial_keypoints [B,V,J,2] f32
//   output: scalar f32
//
// Grid 1024 x 256 (one wave at occ 7). Block = 8 batches, processed as two
// 4-batch chunks in a register-accumulating loop. Warp covers a half-batch:
// lane -> view v (4/warp), kp-group g (4 kps). Smooth-MSE select uses the
// exact identity d' = min(d, d^0.1 * 100^0.9) (curves cross at d=100).

#define BB 8192
#define VV 8
#define JJ 32
#define NBLK 1024
#define POW_C 63.095734448019324f    // 100^0.9

__device__ __align__(16) float g_partials[NBLK];
__device__ unsigned g_count = 0;     // self-resetting completion counter

__global__ __launch_bounds__(256, 7) void qpl_fused(
    const float* __restrict__ K_g,
    const float* __restrict__ cam_g,
    const float* __restrict__ kps_g,
    const float* __restrict__ init_g,
    float* __restrict__ out)
{
    const int tid  = threadIdx.x;
    const int wid  = tid >> 5;
    const int lane = tid & 31;
    const int bi   = wid >> 1;                       // batch within chunk (0..3)
    const int v    = ((wid & 1) << 2) + (lane >> 3); // view 0..7
    const int g    = lane & 7;                       // kp group (4 kps)

    // ---- cooperative staging for the block's 8 batches ----
    __shared__ float4 s_kps4[192];                   // 8 batches * 24 float4
    __shared__ float4 s_cam4[192];                   // 8 batches * 24 float4
    __shared__ float  s_K[768];                      // 8*8 views * 12 (9 used)
    __shared__ float  sh[8];
    __shared__ float  ws[8];
    __shared__ bool   isLast;

    const size_t b0 = (size_t)blockIdx.x * 8;
    if (tid < 192) {
        s_kps4[tid] = reinterpret_cast<const float4*>(kps_g + b0 * (JJ * 3))[tid];
        s_cam4[tid] = reinterpret_cast<const float4*>(cam_g + b0 * (VV * 12))[tid];
    }
    #pragma unroll
    for (int it = 0; it < 3; it++) {
        int i = tid + it * 256;                      // 576 K floats -> padded slots
        if (i < 576) {
            int q = i / 9, r = i - q * 9;
            s_K[q * 12 + r] = K_g[b0 * (VV * 9) + i];
        }
    }
    __syncthreads();

    float loss_acc = 0.0f;

    #pragma unroll 1
    for (int cc = 0; cc < 2; cc++) {
        const int bc = cc * 4 + bi;                  // batch within block (0..7)
        const size_t b = b0 + bc;

        // init keypoints: direct DRAM stream
        const float4* i4 = reinterpret_cast<const float4*>(
            init_g + ((b * VV + v) * JJ + g * 4) * 2);
        const float4 iA = i4[0], iB = i4[1];

        const float4 kA = s_kps4[bc * 24 + g * 3 + 0];
        const float4 kB = s_kps4[bc * 24 + g * 3 + 1];
        const float4 kC = s_kps4[bc * 24 + g * 3 + 2];

        const float4 c0 = s_cam4[bc * 24 + v * 3 + 0];
        const float4 c1 = s_cam4[bc * 24 + v * 3 + 1];
        const float4 c2 = s_cam4[bc * 24 + v * 3 + 2];

        const float4 kq0 = *reinterpret_cast<const float4*>(s_K + (bc * 8 + v) * 12);
        const float4 kq1 = *reinterpret_cast<const float4*>(s_K + (bc * 8 + v) * 12 + 4);
        const float  k8  = s_K[(bc * 8 + v) * 12 + 8];
        const float k0 = kq0.x, k1 = kq0.y, k2 = kq0.z, k3 = kq0.w;
        const float k4 = kq1.x, k5 = kq1.y, k6 = kq1.z, k7 = kq1.w;

        // M = K(3x3) @ cam(3x4)
        const float m00 = fmaf(k0, c0.x, fmaf(k1, c1.x, k2 * c2.x));
        const float m01 = fmaf(k0, c0.y, fmaf(k1, c1.y, k2 * c2.y));
        const float m02 = fmaf(k0, c0.z, fmaf(k1, c1.z, k2 * c2.z));
        const float m03 = fmaf(k0, c0.w, fmaf(k1, c1.w, k2 * c2.w));
        const float m10 = fmaf(k3, c0.x, fmaf(k4, c1.x, k5 * c2.x));
        const float m11 = fmaf(k3, c0.y, fmaf(k4, c1.y, k5 * c2.y));
        const float m12 = fmaf(k3, c0.z, fmaf(k4, c1.z, k5 * c2.z));
        const float m13 = fmaf(k3, c0.w, fmaf(k4, c1.w, k5 * c2.w));
        const float m20 = fmaf(k6, c0.x, fmaf(k7, c1.x, k8 * c2.x));
        const float m21 = fmaf(k6, c0.y, fmaf(k7, c1.y, k8 * c2.y));
        const float m22 = fmaf(k6, c0.z, fmaf(k7, c1.z, k8 * c2.z));
        const float m23 = fmaf(k6, c0.w, fmaf(k7, c1.w, k8 * c2.w));

        float s_pn = 0.0f, s_in = 0.0f, s_d = 0.0f;

#define KP_STEP(X, Y, Z, IX, IY) do {                                          \
        const float i0_ = fmaf(m00, (X), fmaf(m01, (Y), fmaf(m02, (Z), m03))); \
        const float i1_ = fmaf(m10, (X), fmaf(m11, (Y), fmaf(m12, (Z), m13))); \
        const float i2_ = fmaf(m20, (X), fmaf(m21, (Y), fmaf(m22, (Z), m23))); \
        const float inv_ = __fdividef(1.0f, i2_);                              \
        const float px_ = i0_ * inv_;                                          \
        const float py_ = i1_ * inv_;                                          \
        s_pn = fmaf(px_, px_, fmaf(py_, py_, s_pn));                           \
        s_in = fmaf((IX), (IX), fmaf((IY), (IY), s_in));                       \
        float dx_ = (px_ - (IX)) * 0.1f; dx_ *= dx_;                           \
        float dy_ = (py_ - (IY)) * 0.1f; dy_ *= dy_;                           \
        dx_ = fminf(dx_, __powf(dx_, 0.1f) * POW_C);                           \
        dy_ = fminf(dy_, __powf(dy_, 0.1f) * POW_C);                           \
        s_d += dx_ + dy_;                                                      \
    } while (0)

        KP_STEP(kA.x, kA.y, kA.z, iA.x, iA.y);
        KP_STEP(kA.w, kB.x, kB.y, iA.z, iA.w);
        KP_STEP(kB.z, kB.w, kC.x, iB.x, iB.y);
        KP_STEP(kC.y, kC.z, kC.w, iB.z, iB.w);
#undef KP_STEP

        // reduce over g (lane bits 0..2 = same view)
        #pragma unroll
        for (int o = 1; o <= 4; o <<= 1) {
            s_pn += __shfl_xor_sync(0xffffffffu, s_pn, o);
            s_in += __shfl_xor_sync(0xffffffffu, s_in, o);
            s_d  += __shfl_xor_sync(0xffffffffu, s_d,  o);
        }

        const float penal = fabsf(sqrtf(s_pn) * rsqrtf(s_in) - 1.0f);
        float loss = 0.5f * s_d * penal;

        // sum this warp's 4 views (lane bits 3,4)
        loss += __shfl_xor_sync(0xffffffffu, loss, 8);
        loss += __shfl_xor_sync(0xffffffffu, loss, 16);

        loss_acc += loss;                            // lane 0's value is used
    }

    if (lane == 0) sh[wid] = loss_acc;
    __syncthreads();

    if (tid == 0) {
        float t = 0.0f;
        #pragma unroll
        for (int i = 0; i < 8; i++) t += sh[i];      // fixed order
        g_partials[blockIdx.x] = t;
        __threadfence();
        unsigned old = atomicAdd(&g_count, 1u);
        isLast = (old == (unsigned)(gridDim.x - 1));
    }
    __syncthreads();

    // ---- last block: deterministic float shuffle-tree over 1024 partials ----
    if (isLast) {
        const float4 p = reinterpret_cast<const float4*>(g_partials)[tid];
        float a = ((p.x + p.y) + p.z) + p.w;         // fixed order
        #pragma unroll
        for (int o = 16; o; o >>= 1)
            a += __shfl_xor_sync(0xffffffffu, a, o);
        if (lane == 0) ws[wid] = a;
        __syncthreads();
        if (wid == 0) {
            float w = (lane < 8) ? ws[lane] : 0.0f;
            w += __shfl_xor_sync(0xffffffffu, w, 1);
            w += __shfl_xor_sync(0xffffffffu, w, 2);
            w += __shfl_xor_sync(0xffffffffu, w, 4);
            if (lane == 0) {
                out[0] = w * (1.0f / 65536.0f);      // / (B*V), exact pow2
                g_count = 0;                         // reset for next graph replay
            }
        }
    }
}

extern "C" void kernel_launch(void* const* d_in, const int* in_sizes, int n_in,
                              void* d_out, int out_size)
{
    const float* K    = (const float*)d_in[0];
    const float* cam  = (const float*)d_in[1];
    const float* kps  = (const float*)d_in[2];
    const float* init = (const float*)d_in[3];

    qpl_fused<<<NBLK, 256>>>(K, cam, kps, init, (float*)d_out);
}